// round 9
// baseline (speedup 1.0000x reference)
#include <cuda_runtime.h>
#include <cuda_fp16.h>
#include <cstdint>
#include <math.h>

#define Bdim 64
#define Idim 2048
#define Hdim 2048
#define Tdim 128
#define Mtot (Tdim * Bdim)          // 8192 rows (t,b)

// ---------------- scratch (device globals; allocation-free) ----------------
__device__ __half g_Ah[(size_t)Mtot * Idim];          // 32 MB  [t*B+b][i]
__device__ __half g_w0[(size_t)Hdim * Idim];          // 8 MB   hi plane [h][i]
__device__ __half g_w1[(size_t)Hdim * Idim];          // 8 MB   res*2^11 [h][i]
__device__ float  g_weightedT[(size_t)Tdim * Hdim * Bdim];  // 64 MB [t][h][b]

// ---------------------------------------------------------------------------
// Fused prep: blocks [0,16384): spike transpose+convert; [16384,20480): split.
// ---------------------------------------------------------------------------
__global__ void prep_kernel(const float* __restrict__ in,
                            const float* __restrict__ w,
                            const float* __restrict__ s) {
    __shared__ float tile[32][33];
    int bid = blockIdx.x;
    int tx = threadIdx.x, ty = threadIdx.y;

    if (bid < 16384) {
        int t0 = (bid & 3) * 32;
        int i0 = ((bid >> 2) & 63) * 32;
        int b  = bid >> 8;
#pragma unroll
        for (int j = 0; j < 32; j += 8)
            tile[ty + j][tx] = in[((size_t)b * Idim + i0 + ty + j) * Tdim + t0 + tx];
        __syncthreads();
#pragma unroll
        for (int j = 0; j < 32; j += 8)
            g_Ah[((size_t)(t0 + ty + j) * Bdim + b) * Idim + i0 + tx] =
                __float2half_rn(tile[tx][ty + j]);
    } else {
        int sid = bid - 16384;
        int i0 = (sid & 63) * 32;
        int h0 = (sid >> 6) * 32;
#pragma unroll
        for (int j = 0; j < 32; j += 8) {
            size_t idx = (size_t)(i0 + ty + j) * Hdim + h0 + tx;
            tile[ty + j][tx] = w[idx] * s[idx];
        }
        __syncthreads();
#pragma unroll
        for (int j = 0; j < 32; j += 8) {
            float v = tile[tx][ty + j];                 // [i=tx][h=ty+j]
            __half hi = __float2half_rn(v);
            float r = v - __half2float(hi);             // exact (Fast2Sum)
            __half lo = __float2half_rn(r * 2048.0f);
            size_t o = (size_t)(h0 + ty + j) * Idim + i0 + tx;
            g_w0[o] = hi;
            g_w1[o] = lo;
        }
    }
}

// ---------------------------------------------------------------------------
// mma.sync GEMM: C = A @ W0^T + 2^-11 * (A @ W1^T).
// Pass0 (kt 0..31, residual plane): fp16 accumulators (2x issue rate if rt=8).
// Pass1 (kt 32..63, hi plane): fp32 accumulators.
// CTA 128x256, BK=64, 512 threads, 3-stage cp.async, ldmatrix.x4.
// ---------------------------------------------------------------------------
#define BM 128
#define BN 256
#define BK 64
#define ASTR 72                          // halves per smem row (144 B)
#define A_STG_H (BM * ASTR)
#define B_STG_H (BN * ASTR)
#define STAGE_BYTES ((A_STG_H + B_STG_H) * 2)   // 55296 B
#define GEMM_SMEM (3 * STAGE_BYTES)             // 165888 B
#define NKT 64
#define EPI_STR 65

__device__ __forceinline__ void ldsm_x4(uint32_t* r, uint32_t addr) {
    asm volatile("ldmatrix.sync.aligned.m8n8.x4.shared.b16 {%0,%1,%2,%3}, [%4];"
                 : "=r"(r[0]), "=r"(r[1]), "=r"(r[2]), "=r"(r[3]) : "r"(addr));
}

__device__ __forceinline__ void stage_load(uint32_t sbase, int stage, int kt,
                                           int tid, int m0, int n0) {
    const __half* Asrc = g_Ah + (size_t)m0 * Idim;
    const __half* Bsrc = (kt < 32 ? g_w1 : g_w0) + (size_t)n0 * Idim;
    int k0 = (kt & 31) * BK;
    uint32_t sA = sbase + (uint32_t)stage * STAGE_BYTES;
    uint32_t sB = sA + A_STG_H * 2;
#pragma unroll
    for (int i = 0; i < 2; i++) {
        int ch = tid + i * 512;
        int r = ch >> 3, c = ch & 7;
        uint32_t d = sA + (uint32_t)(r * ASTR + c * 8) * 2;
        asm volatile("cp.async.cg.shared.global [%0], [%1], 16;"
                     :: "r"(d), "l"(Asrc + (size_t)r * Idim + k0 + c * 8));
    }
#pragma unroll
    for (int i = 0; i < 4; i++) {
        int ch = tid + i * 512;
        int r = ch >> 3, c = ch & 7;
        uint32_t d = sB + (uint32_t)(r * ASTR + c * 8) * 2;
        asm volatile("cp.async.cg.shared.global [%0], [%1], 16;"
                     :: "r"(d), "l"(Bsrc + (size_t)r * Idim + k0 + c * 8));
    }
}

__global__ __launch_bounds__(512, 1) void gemm_mma_kernel() {
    extern __shared__ char smem[];
    uint32_t sbase = (uint32_t)__cvta_generic_to_shared(smem);

    int tid  = threadIdx.x;
    int lane = tid & 31;
    int wid  = tid >> 5;
    int wm = (wid >> 2) * 32;
    int wn = (wid & 3) * 64;
    int lr = lane >> 2;
    int lc = lane & 3;
    int m0 = blockIdx.y * BM;
    int n0 = blockIdx.x * BN;

    int a_row  = wm + (lane & 15);
    int a_csel = (lane >> 4) << 3;
    int b_row  = ((lane >> 4) << 3) + (lane & 7);
    int b_csel = ((lane >> 3) & 1) << 3;

    uint32_t acc16[2][8][2];                 // fp16x2 accumulators (pass0)
#pragma unroll
    for (int mt = 0; mt < 2; mt++)
#pragma unroll
        for (int nt = 0; nt < 8; nt++) { acc16[mt][nt][0] = 0u; acc16[mt][nt][1] = 0u; }

    stage_load(sbase, 0, 0, tid, m0, n0);
    asm volatile("cp.async.commit_group;" ::: "memory");
    stage_load(sbase, 1, 1, tid, m0, n0);
    asm volatile("cp.async.commit_group;" ::: "memory");

    // ---- Pass 0: residual plane, fp16 accumulation ----
#pragma unroll 1
    for (int kt = 0; kt < 32; kt++) {
        asm volatile("cp.async.wait_group 1;" ::: "memory");
        __syncthreads();
        stage_load(sbase, (kt + 2) % 3, kt + 2, tid, m0, n0);
        asm volatile("cp.async.commit_group;" ::: "memory");

        uint32_t stA = sbase + (uint32_t)(kt % 3) * STAGE_BYTES;
        uint32_t stB = stA + A_STG_H * 2;
#pragma unroll
        for (int ks = 0; ks < 4; ks++) {
            int kb = ks * 16;
            uint32_t a[2][4];
#pragma unroll
            for (int mt = 0; mt < 2; mt++)
                ldsm_x4(a[mt], stA + (uint32_t)((a_row + mt * 16) * ASTR + kb + a_csel) * 2);
            uint32_t bf[8][2];
#pragma unroll
            for (int p = 0; p < 4; p++) {
                uint32_t r[4];
                ldsm_x4(r, stB + (uint32_t)((wn + p * 16 + b_row) * ASTR + kb + b_csel) * 2);
                bf[2 * p][0] = r[0]; bf[2 * p][1] = r[1];
                bf[2 * p + 1][0] = r[2]; bf[2 * p + 1][1] = r[3];
            }
#pragma unroll
            for (int nt = 0; nt < 8; nt++)
#pragma unroll
                for (int mt = 0; mt < 2; mt++) {
                    uint32_t* c = acc16[mt][nt];
                    asm volatile(
                        "mma.sync.aligned.m16n8k16.row.col.f16.f16.f16.f16 "
                        "{%0,%1}, {%2,%3,%4,%5}, {%6,%7}, {%0,%1};"
                        : "+r"(c[0]), "+r"(c[1])
                        : "r"(a[mt][0]), "r"(a[mt][1]), "r"(a[mt][2]), "r"(a[mt][3]),
                          "r"(bf[nt][0]), "r"(bf[nt][1]));
                }
        }
    }

    // ---- Boundary: acc = 2^-11 * C_res (convert fp16 -> fp32, exact scale) ----
    float acc[2][8][4];
#pragma unroll
    for (int mt = 0; mt < 2; mt++)
#pragma unroll
        for (int nt = 0; nt < 8; nt++) {
            __half2 h0 = *reinterpret_cast<__half2*>(&acc16[mt][nt][0]);
            __half2 h1 = *reinterpret_cast<__half2*>(&acc16[mt][nt][1]);
            float2 f0 = __half22float2(h0);
            float2 f1 = __half22float2(h1);
            acc[mt][nt][0] = f0.x * 4.8828125e-4f;
            acc[mt][nt][1] = f0.y * 4.8828125e-4f;
            acc[mt][nt][2] = f1.x * 4.8828125e-4f;
            acc[mt][nt][3] = f1.y * 4.8828125e-4f;
        }

    // ---- Pass 1: hi plane, fp32 accumulation ----
#pragma unroll 1
    for (int kt = 32; kt < NKT; kt++) {
        asm volatile("cp.async.wait_group 1;" ::: "memory");
        __syncthreads();
        if (kt + 2 < NKT)
            stage_load(sbase, (kt + 2) % 3, kt + 2, tid, m0, n0);
        asm volatile("cp.async.commit_group;" ::: "memory");

        uint32_t stA = sbase + (uint32_t)(kt % 3) * STAGE_BYTES;
        uint32_t stB = stA + A_STG_H * 2;
#pragma unroll
        for (int ks = 0; ks < 4; ks++) {
            int kb = ks * 16;
            uint32_t a[2][4];
#pragma unroll
            for (int mt = 0; mt < 2; mt++)
                ldsm_x4(a[mt], stA + (uint32_t)((a_row + mt * 16) * ASTR + kb + a_csel) * 2);
            uint32_t bf[8][2];
#pragma unroll
            for (int p = 0; p < 4; p++) {
                uint32_t r[4];
                ldsm_x4(r, stB + (uint32_t)((wn + p * 16 + b_row) * ASTR + kb + b_csel) * 2);
                bf[2 * p][0] = r[0]; bf[2 * p][1] = r[1];
                bf[2 * p + 1][0] = r[2]; bf[2 * p + 1][1] = r[3];
            }
#pragma unroll
            for (int nt = 0; nt < 8; nt++)
#pragma unroll
                for (int mt = 0; mt < 2; mt++) {
                    float* c = acc[mt][nt];
                    asm volatile(
                        "mma.sync.aligned.m16n8k16.row.col.f32.f16.f16.f32 "
                        "{%0,%1,%2,%3}, {%4,%5,%6,%7}, {%8,%9}, {%0,%1,%2,%3};"
                        : "+f"(c[0]), "+f"(c[1]), "+f"(c[2]), "+f"(c[3])
                        : "r"(a[mt][0]), "r"(a[mt][1]), "r"(a[mt][2]), "r"(a[mt][3]),
                          "r"(bf[nt][0]), "r"(bf[nt][1]));
                }
        }
    }

    // ---- Epilogue: stage through smem as [t_local][h][b], write coalesced ----
    __syncthreads();
    float* epi = reinterpret_cast<float*>(smem);   // [2][256][EPI_STR]
#pragma unroll
    for (int mt = 0; mt < 2; mt++) {
#pragma unroll
        for (int q2 = 0; q2 < 2; q2++) {
            int row = wm + mt * 16 + lr + q2 * 8;   // local row 0..127
            int tl = row >> 6, bb = row & 63;
#pragma unroll
            for (int nt = 0; nt < 8; nt++) {
                int col = wn + nt * 8 + lc * 2;
                epi[((size_t)(tl * 256 + col)     * EPI_STR) + bb] = acc[mt][nt][q2 * 2 + 0];
                epi[((size_t)(tl * 256 + col + 1) * EPI_STR) + bb] = acc[mt][nt][q2 * 2 + 1];
            }
        }
    }
    __syncthreads();
    {
        int tl = tid >> 8;
        int h  = tid & 255;
        int t_glob = blockIdx.y * 2 + tl;
        float* dst = g_weightedT + ((size_t)t_glob * Hdim + n0 + h) * Bdim;
        const float* src = epi + (size_t)(tl * 256 + h) * EPI_STR;
#pragma unroll
        for (int j = 0; j < 64; j += 4) {
            float4 o;
            o.x = src[j]; o.y = src[j + 1]; o.z = src[j + 2]; o.w = src[j + 3];
            *reinterpret_cast<float4*>(dst + j) = o;
        }
    }
}

// ---------------------------------------------------------------------------
// LIF scan: one warp per h, lanes own b = 2*lane, 2*lane+1. (R8 verbatim)
// ---------------------------------------------------------------------------
__global__ __launch_bounds__(256) void scan_kernel(
    const float* __restrict__ threshold,
    const float* __restrict__ p_tau_mem, const float* __restrict__ p_tau_syn,
    const float* __restrict__ p_target,  const float* __restrict__ p_lr,
    float* __restrict__ out)
{
    int tid  = threadIdx.x;
    int lane = tid & 31;
    int h    = blockIdx.x * 8 + (tid >> 5);

    float tau_m = *p_tau_mem, tau_s = *p_tau_syn;
    float a_mem = (float)exp(-(double)(0.001f / tau_m));
    float a_syn = (float)exp(-(double)(0.001f / tau_s));
    float target = *p_target, lr = *p_lr;

    float thr = threshold[h];
    float fre = 0.0f;
    float isyn0 = 0.0f, v0 = 0.0f, isyn1 = 0.0f, v1 = 0.0f;
    unsigned sb0[4] = {0u, 0u, 0u, 0u};
    unsigned sb1[4] = {0u, 0u, 0u, 0u};

    const float* wptr = g_weightedT + (size_t)h * Bdim + lane * 2;
    const size_t TSTR = (size_t)Hdim * Bdim;

    float2 wbuf[4];
#pragma unroll
    for (int p = 0; p < 4; p++)
        wbuf[p] = *reinterpret_cast<const float2*>(wptr + p * TSTR);

#pragma unroll 4
    for (int t = 0; t < Tdim; ++t) {
        float2 w = wbuf[0];
        wbuf[0] = wbuf[1]; wbuf[1] = wbuf[2]; wbuf[2] = wbuf[3];
        if (t + 4 < Tdim)
            wbuf[3] = *reinterpret_cast<const float2*>(wptr + (size_t)(t + 4) * TSTR);

        isyn0 = fmaf(a_syn, isyn0, w.x);
        v0    = fmaf(a_mem, v0, isyn0);
        isyn1 = fmaf(a_syn, isyn1, w.y);
        v1    = fmaf(a_mem, v1, isyn1);
        bool p0 = (v0 >= thr), p1 = (v1 >= thr);
        if (p0) { v0 -= thr; sb0[t >> 5] |= (1u << (t & 31)); }
        if (p1) { v1 -= thr; sb1[t >> 5] |= (1u << (t & 31)); }

        unsigned m0 = __ballot_sync(0xffffffffu, p0);
        unsigned m1 = __ballot_sync(0xffffffffu, p1);
        float s = (float)(__popc(m0) + __popc(m1));      // exact int

        float rate = s * (1.0f / 64.0f);
        fre = 0.99f * fre + 0.01f * rate;
        thr = thr + lr * (fre - target);
    }

    int bsel = (lane & 7) * 4;
#pragma unroll 4
    for (int bb = 0; bb < 64; ++bb) {
        int src = bb >> 1;
        unsigned w0, w1, w2, w3;
        if (bb & 1) {
            w0 = __shfl_sync(0xffffffffu, sb1[0], src);
            w1 = __shfl_sync(0xffffffffu, sb1[1], src);
            w2 = __shfl_sync(0xffffffffu, sb1[2], src);
            w3 = __shfl_sync(0xffffffffu, sb1[3], src);
        } else {
            w0 = __shfl_sync(0xffffffffu, sb0[0], src);
            w1 = __shfl_sync(0xffffffffu, sb0[1], src);
            w2 = __shfl_sync(0xffffffffu, sb0[2], src);
            w3 = __shfl_sync(0xffffffffu, sb0[3], src);
        }
        unsigned wsel = (lane < 8) ? w0 : (lane < 16) ? w1 : (lane < 24) ? w2 : w3;
        unsigned bits = (wsel >> bsel) & 0xFu;
        float4 o;
        o.x = (float)(bits & 1u);
        o.y = (float)((bits >> 1) & 1u);
        o.z = (float)((bits >> 2) & 1u);
        o.w = (float)((bits >> 3) & 1u);
        *reinterpret_cast<float4*>(
            out + ((size_t)bb * Hdim + h) * Tdim + lane * 4) = o;
    }
}

// ---------------------------------------------------------------------------
extern "C" void kernel_launch(void* const* d_in, const int* in_sizes, int n_in,
                              void* d_out, int out_size) {
    const float* spikes    = (const float*)d_in[0];
    const float* weight    = (const float*)d_in[1];
    const float* strength  = (const float*)d_in[2];
    const float* threshold = (const float*)d_in[3];
    const float* tau_mem   = (const float*)d_in[4];
    const float* tau_syn   = (const float*)d_in[5];
    const float* target    = (const float*)d_in[6];
    const float* lr        = (const float*)d_in[7];
    float* out = (float*)d_out;

    cudaFuncSetAttribute(gemm_mma_kernel,
                         cudaFuncAttributeMaxDynamicSharedMemorySize, GEMM_SMEM);

    prep_kernel<<<20480, dim3(32, 8)>>>(spikes, weight, strength);
    gemm_mma_kernel<<<dim3(Hdim / BN, Mtot / BM), 512, GEMM_SMEM>>>();
    scan_kernel<<<Hdim / 8, 256>>>(threshold, tau_mem, tau_syn, target, lr, out);
}

// round 10
// speedup vs baseline: 1.1660x; 1.1660x over previous
#include <cuda_runtime.h>
#include <cuda_fp16.h>
#include <cstdint>
#include <math.h>

#define Bdim 64
#define Idim 2048
#define Hdim 2048
#define Tdim 128
#define Mtot (Tdim * Bdim)          // 8192 rows (t,b)

// ---------------- scratch (device globals; allocation-free) ----------------
__device__ __half g_Ah[(size_t)Mtot * Idim];          // 32 MB  [t*B+b][i]
__device__ __half g_w0[(size_t)Hdim * Idim];          // 8 MB   hi plane [h][i]
__device__ __half g_w1[(size_t)Hdim * Idim];          // 8 MB   res*2^11 [h][i]
__device__ float  g_weightedT[(size_t)Tdim * Hdim * Bdim];  // 64 MB [t][h][b]

// ---------------------------------------------------------------------------
// Fused prep: blocks [0,16384): spike transpose+convert; [16384,20480): split.
// ---------------------------------------------------------------------------
__global__ void prep_kernel(const float* __restrict__ in,
                            const float* __restrict__ w,
                            const float* __restrict__ s) {
    __shared__ float tile[32][33];
    int bid = blockIdx.x;
    int tx = threadIdx.x, ty = threadIdx.y;

    if (bid < 16384) {
        int t0 = (bid & 3) * 32;
        int i0 = ((bid >> 2) & 63) * 32;
        int b  = bid >> 8;
#pragma unroll
        for (int j = 0; j < 32; j += 8)
            tile[ty + j][tx] = in[((size_t)b * Idim + i0 + ty + j) * Tdim + t0 + tx];
        __syncthreads();
#pragma unroll
        for (int j = 0; j < 32; j += 8)
            g_Ah[((size_t)(t0 + ty + j) * Bdim + b) * Idim + i0 + tx] =
                __float2half_rn(tile[tx][ty + j]);
    } else {
        int sid = bid - 16384;
        int i0 = (sid & 63) * 32;
        int h0 = (sid >> 6) * 32;
#pragma unroll
        for (int j = 0; j < 32; j += 8) {
            size_t idx = (size_t)(i0 + ty + j) * Hdim + h0 + tx;
            tile[ty + j][tx] = w[idx] * s[idx];
        }
        __syncthreads();
#pragma unroll
        for (int j = 0; j < 32; j += 8) {
            float v = tile[tx][ty + j];                 // [i=tx][h=ty+j]
            __half hi = __float2half_rn(v);
            float r = v - __half2float(hi);             // exact (Fast2Sum)
            __half lo = __float2half_rn(r * 2048.0f);
            size_t o = (size_t)(h0 + ty + j) * Idim + i0 + tx;
            g_w0[o] = hi;
            g_w1[o] = lo;
        }
    }
}

// ---------------------------------------------------------------------------
// mma.sync GEMM: C = A @ W0^T + 2^-11 * (A @ W1^T), fp32 acc (R8 arithmetic).
// CTA 128x128, BK=64, 256 threads (8 warps, warp tile 32x64), 3-stage
// cp.async pipeline, ldmatrix.x4, fused 64-kt loop (plane switch at kt=32).
// 2 CTAs/SM (110.6 KB smem each) to kill tail-wave quantization.
// ---------------------------------------------------------------------------
#define BM 128
#define BN 128
#define BK 64
#define ASTR 72                          // halves per smem row (144 B)
#define A_STG_H (BM * ASTR)              // 9216 halves
#define B_STG_H (BN * ASTR)              // 9216 halves
#define STAGE_BYTES ((A_STG_H + B_STG_H) * 2)   // 36864 B
#define GEMM_SMEM (3 * STAGE_BYTES)             // 110592 B
#define NKT 64
#define EPI_STR 65

__device__ __forceinline__ void ldsm_x4(uint32_t* r, uint32_t addr) {
    asm volatile("ldmatrix.sync.aligned.m8n8.x4.shared.b16 {%0,%1,%2,%3}, [%4];"
                 : "=r"(r[0]), "=r"(r[1]), "=r"(r[2]), "=r"(r[3]) : "r"(addr));
}

__device__ __forceinline__ void stage_load(uint32_t sbase, int stage, int kt,
                                           int tid, int m0, int n0) {
    const __half* Asrc = g_Ah + (size_t)m0 * Idim;
    const __half* Bsrc = (kt < 32 ? g_w1 : g_w0) + (size_t)n0 * Idim;
    int k0 = (kt & 31) * BK;
    uint32_t sA = sbase + (uint32_t)stage * STAGE_BYTES;
    uint32_t sB = sA + A_STG_H * 2;
#pragma unroll
    for (int i = 0; i < 4; i++) {               // A: 128 rows x 8 chunks16B
        int ch = tid + i * 256;
        int r = ch >> 3, c = ch & 7;
        uint32_t d = sA + (uint32_t)(r * ASTR + c * 8) * 2;
        asm volatile("cp.async.cg.shared.global [%0], [%1], 16;"
                     :: "r"(d), "l"(Asrc + (size_t)r * Idim + k0 + c * 8));
    }
#pragma unroll
    for (int i = 0; i < 4; i++) {               // B: 128 rows x 8 chunks16B
        int ch = tid + i * 256;
        int r = ch >> 3, c = ch & 7;
        uint32_t d = sB + (uint32_t)(r * ASTR + c * 8) * 2;
        asm volatile("cp.async.cg.shared.global [%0], [%1], 16;"
                     :: "r"(d), "l"(Bsrc + (size_t)r * Idim + k0 + c * 8));
    }
}

__global__ __launch_bounds__(256, 2) void gemm_mma_kernel() {
    extern __shared__ char smem[];
    uint32_t sbase = (uint32_t)__cvta_generic_to_shared(smem);

    int tid  = threadIdx.x;
    int lane = tid & 31;
    int wid  = tid >> 5;
    int wm = (wid >> 1) * 32;            // 0,32,64,96
    int wn = (wid & 1) * 64;             // 0,64
    int lr = lane >> 2;
    int lc = lane & 3;
    int m0 = blockIdx.y * BM;
    int n0 = blockIdx.x * BN;

    int a_row  = wm + (lane & 15);
    int a_csel = (lane >> 4) << 3;
    int b_row  = ((lane >> 4) << 3) + (lane & 7);
    int b_csel = ((lane >> 3) & 1) << 3;

    float acc[2][8][4];
#pragma unroll
    for (int mt = 0; mt < 2; mt++)
#pragma unroll
        for (int nt = 0; nt < 8; nt++)
#pragma unroll
            for (int q = 0; q < 4; q++) acc[mt][nt][q] = 0.0f;

    stage_load(sbase, 0, 0, tid, m0, n0);
    asm volatile("cp.async.commit_group;" ::: "memory");
    stage_load(sbase, 1, 1, tid, m0, n0);
    asm volatile("cp.async.commit_group;" ::: "memory");

#pragma unroll 1
    for (int kt = 0; kt < NKT; kt++) {
        asm volatile("cp.async.wait_group 1;" ::: "memory");
        __syncthreads();

        if (kt + 2 < NKT)
            stage_load(sbase, (kt + 2) % 3, kt + 2, tid, m0, n0);
        asm volatile("cp.async.commit_group;" ::: "memory");

        if (kt == 32) {                  // pass boundary: acc = 2^-11 * C_res
#pragma unroll
            for (int mt = 0; mt < 2; mt++)
#pragma unroll
                for (int nt = 0; nt < 8; nt++)
#pragma unroll
                    for (int q = 0; q < 4; q++) acc[mt][nt][q] *= 4.8828125e-4f;
        }

        uint32_t stA = sbase + (uint32_t)(kt % 3) * STAGE_BYTES;
        uint32_t stB = stA + A_STG_H * 2;
#pragma unroll
        for (int ks = 0; ks < 4; ks++) {
            int kb = ks * 16;
            uint32_t a[2][4];
#pragma unroll
            for (int mt = 0; mt < 2; mt++)
                ldsm_x4(a[mt], stA + (uint32_t)((a_row + mt * 16) * ASTR + kb + a_csel) * 2);
            uint32_t bf[8][2];
#pragma unroll
            for (int p = 0; p < 4; p++) {
                uint32_t r[4];
                ldsm_x4(r, stB + (uint32_t)((wn + p * 16 + b_row) * ASTR + kb + b_csel) * 2);
                bf[2 * p][0] = r[0]; bf[2 * p][1] = r[1];
                bf[2 * p + 1][0] = r[2]; bf[2 * p + 1][1] = r[3];
            }
#pragma unroll
            for (int nt = 0; nt < 8; nt++)
#pragma unroll
                for (int mt = 0; mt < 2; mt++) {
                    float* c = acc[mt][nt];
                    asm volatile(
                        "mma.sync.aligned.m16n8k16.row.col.f32.f16.f16.f32 "
                        "{%0,%1,%2,%3}, {%4,%5,%6,%7}, {%8,%9}, {%0,%1,%2,%3};"
                        : "+f"(c[0]), "+f"(c[1]), "+f"(c[2]), "+f"(c[3])
                        : "r"(a[mt][0]), "r"(a[mt][1]), "r"(a[mt][2]), "r"(a[mt][3]),
                          "r"(bf[nt][0]), "r"(bf[nt][1]));
                }
        }
    }

    // ---- Epilogue: stage through smem as [t_local][h][b], write coalesced ----
    __syncthreads();
    float* epi = reinterpret_cast<float*>(smem);   // [2][128][EPI_STR]
#pragma unroll
    for (int mt = 0; mt < 2; mt++) {
#pragma unroll
        for (int q2 = 0; q2 < 2; q2++) {
            int row = wm + mt * 16 + lr + q2 * 8;   // local row 0..127
            int tl = row >> 6, bb = row & 63;
#pragma unroll
            for (int nt = 0; nt < 8; nt++) {
                int col = wn + nt * 8 + lc * 2;
                epi[((size_t)(tl * 128 + col)     * EPI_STR) + bb] = acc[mt][nt][q2 * 2 + 0];
                epi[((size_t)(tl * 128 + col + 1) * EPI_STR) + bb] = acc[mt][nt][q2 * 2 + 1];
            }
        }
    }
    __syncthreads();
    {
        int tl = tid >> 7;                 // 0..1
        int h  = tid & 127;                // 0..127
        int t_glob = blockIdx.y * 2 + tl;
        float* dst = g_weightedT + ((size_t)t_glob * Hdim + n0 + h) * Bdim;
        const float* src = epi + (size_t)(tl * 128 + h) * EPI_STR;
#pragma unroll
        for (int j = 0; j < 64; j += 4) {
            float4 o;
            o.x = src[j]; o.y = src[j + 1]; o.z = src[j + 2]; o.w = src[j + 3];
            *reinterpret_cast<float4*>(dst + j) = o;
        }
    }
}

// ---------------------------------------------------------------------------
// LIF scan: one warp per h, lanes own b = 2*lane, 2*lane+1. (R8 verbatim)
// ---------------------------------------------------------------------------
__global__ __launch_bounds__(256) void scan_kernel(
    const float* __restrict__ threshold,
    const float* __restrict__ p_tau_mem, const float* __restrict__ p_tau_syn,
    const float* __restrict__ p_target,  const float* __restrict__ p_lr,
    float* __restrict__ out)
{
    int tid  = threadIdx.x;
    int lane = tid & 31;
    int h    = blockIdx.x * 8 + (tid >> 5);

    float tau_m = *p_tau_mem, tau_s = *p_tau_syn;
    float a_mem = (float)exp(-(double)(0.001f / tau_m));
    float a_syn = (float)exp(-(double)(0.001f / tau_s));
    float target = *p_target, lr = *p_lr;

    float thr = threshold[h];
    float fre = 0.0f;
    float isyn0 = 0.0f, v0 = 0.0f, isyn1 = 0.0f, v1 = 0.0f;
    unsigned sb0[4] = {0u, 0u, 0u, 0u};
    unsigned sb1[4] = {0u, 0u, 0u, 0u};

    const float* wptr = g_weightedT + (size_t)h * Bdim + lane * 2;
    const size_t TSTR = (size_t)Hdim * Bdim;

    float2 wbuf[4];
#pragma unroll
    for (int p = 0; p < 4; p++)
        wbuf[p] = *reinterpret_cast<const float2*>(wptr + p * TSTR);

#pragma unroll 4
    for (int t = 0; t < Tdim; ++t) {
        float2 w = wbuf[0];
        wbuf[0] = wbuf[1]; wbuf[1] = wbuf[2]; wbuf[2] = wbuf[3];
        if (t + 4 < Tdim)
            wbuf[3] = *reinterpret_cast<const float2*>(wptr + (size_t)(t + 4) * TSTR);

        isyn0 = fmaf(a_syn, isyn0, w.x);
        v0    = fmaf(a_mem, v0, isyn0);
        isyn1 = fmaf(a_syn, isyn1, w.y);
        v1    = fmaf(a_mem, v1, isyn1);
        bool p0 = (v0 >= thr), p1 = (v1 >= thr);
        if (p0) { v0 -= thr; sb0[t >> 5] |= (1u << (t & 31)); }
        if (p1) { v1 -= thr; sb1[t >> 5] |= (1u << (t & 31)); }

        unsigned m0 = __ballot_sync(0xffffffffu, p0);
        unsigned m1 = __ballot_sync(0xffffffffu, p1);
        float s = (float)(__popc(m0) + __popc(m1));      // exact int

        float rate = s * (1.0f / 64.0f);
        fre = 0.99f * fre + 0.01f * rate;
        thr = thr + lr * (fre - target);
    }

    int bsel = (lane & 7) * 4;
#pragma unroll 4
    for (int bb = 0; bb < 64; ++bb) {
        int src = bb >> 1;
        unsigned w0, w1, w2, w3;
        if (bb & 1) {
            w0 = __shfl_sync(0xffffffffu, sb1[0], src);
            w1 = __shfl_sync(0xffffffffu, sb1[1], src);
            w2 = __shfl_sync(0xffffffffu, sb1[2], src);
            w3 = __shfl_sync(0xffffffffu, sb1[3], src);
        } else {
            w0 = __shfl_sync(0xffffffffu, sb0[0], src);
            w1 = __shfl_sync(0xffffffffu, sb0[1], src);
            w2 = __shfl_sync(0xffffffffu, sb0[2], src);
            w3 = __shfl_sync(0xffffffffu, sb0[3], src);
        }
        unsigned wsel = (lane < 8) ? w0 : (lane < 16) ? w1 : (lane < 24) ? w2 : w3;
        unsigned bits = (wsel >> bsel) & 0xFu;
        float4 o;
        o.x = (float)(bits & 1u);
        o.y = (float)((bits >> 1) & 1u);
        o.z = (float)((bits >> 2) & 1u);
        o.w = (float)((bits >> 3) & 1u);
        *reinterpret_cast<float4*>(
            out + ((size_t)bb * Hdim + h) * Tdim + lane * 4) = o;
    }
}

// ---------------------------------------------------------------------------
extern "C" void kernel_launch(void* const* d_in, const int* in_sizes, int n_in,
                              void* d_out, int out_size) {
    const float* spikes    = (const float*)d_in[0];
    const float* weight    = (const float*)d_in[1];
    const float* strength  = (const float*)d_in[2];
    const float* threshold = (const float*)d_in[3];
    const float* tau_mem   = (const float*)d_in[4];
    const float* tau_syn   = (const float*)d_in[5];
    const float* target    = (const float*)d_in[6];
    const float* lr        = (const float*)d_in[7];
    float* out = (float*)d_out;

    cudaFuncSetAttribute(gemm_mma_kernel,
                         cudaFuncAttributeMaxDynamicSharedMemorySize, GEMM_SMEM);

    prep_kernel<<<20480, dim3(32, 8)>>>(spikes, weight, strength);
    gemm_mma_kernel<<<dim3(Hdim / BN, Mtot / BM), 256, GEMM_SMEM>>>();
    scan_kernel<<<Hdim / 8, 256>>>(threshold, tau_mem, tau_syn, target, lr, out);
}